// round 1
// baseline (speedup 1.0000x reference)
#include <cuda_runtime.h>

#define BB    2048
#define ZZ    64
#define AA    8
#define HH    512
#define TT    64
#define FOURH 2048

// Scratch (device globals — no allocation allowed)
__device__ float g_xproj[FOURH * BB];   // [n][b]  16 MB: x_proj transposed, batch contiguous
__device__ float g_WT[HH * FOURH];      // [j][n]   4 MB: W_hh transposed, n contiguous

typedef unsigned long long u64;

__device__ __forceinline__ u64 fma2(u64 a, u64 b, u64 c) {
    u64 d;
    asm("fma.rn.f32x2 %0, %1, %2, %3;" : "=l"(d) : "l"(a), "l"(b), "l"(c));
    return d;
}
__device__ __forceinline__ u64 pack2(float x, float y) {
    u64 d;
    asm("mov.b64 %0, {%1, %2};" : "=l"(d) : "f"(x), "f"(y));
    return d;
}
__device__ __forceinline__ float2 unpack2(u64 v) {
    float2 r;
    asm("mov.b64 {%0, %1}, %2;" : "=f"(r.x), "=f"(r.y) : "l"(v));
    return r;
}

__device__ __forceinline__ float sigf(float x) {
    return __fdividef(1.f, 1.f + __expf(-x));
}
__device__ __forceinline__ float thf(float x) {
    float xx = fminf(fmaxf(x, -15.f), 15.f);
    float e = __expf(-2.f * xx);
    return __fdividef(1.f - e, 1.f + e);
}

// ---------------------------------------------------------------------------
// x_proj[n][b] = b_ih[n] + b_hh[n] + sum_j z[b][j] * W_ih[n][A+j]
// (first A input columns are zeros in the reference -> skipped)
// grid: (B/128, 4H/128), block 256
// ---------------------------------------------------------------------------
__global__ void xproj_kernel(const float* __restrict__ z,
                             const float* __restrict__ W_ih,
                             const float* __restrict__ b_ih,
                             const float* __restrict__ b_hh) {
    __shared__ float zs[128][ZZ + 1];
    const int b0 = blockIdx.x * 128;
    const int n0 = blockIdx.y * 128;
    const int tid = threadIdx.x;

    for (int i = tid; i < 128 * ZZ; i += 256) {
        int bi = i / ZZ, j = i % ZZ;
        zs[bi][j] = z[(b0 + bi) * ZZ + j];
    }
    __syncthreads();

    const int bi = tid & 127;
    const int nhalf = tid >> 7;  // 0..1
    for (int nn = 0; nn < 64; ++nn) {
        const int n = n0 + nhalf * 64 + nn;
        const float* w = W_ih + n * (AA + ZZ) + AA;
        float acc = b_ih[n] + b_hh[n];
#pragma unroll 8
        for (int j = 0; j < ZZ; ++j) acc = fmaf(w[j], zs[bi][j], acc);
        g_xproj[n * BB + b0 + bi] = acc;
    }
}

// ---------------------------------------------------------------------------
// g_WT[j][n] = W_hh[n][j]   (tiled transpose)
// grid: (4H/32, H/32), block (32,8)
// ---------------------------------------------------------------------------
__global__ void transpose_kernel(const float* __restrict__ W_hh) {
    __shared__ float tile[32][33];
    const int n0 = blockIdx.x * 32;
    const int j0 = blockIdx.y * 32;
    const int tx = threadIdx.x, ty = threadIdx.y;
    for (int r = ty; r < 32; r += 8)
        tile[r][tx] = W_hh[(n0 + r) * HH + j0 + tx];
    __syncthreads();
    for (int r = ty; r < 32; r += 8)
        g_WT[(j0 + r) * FOURH + n0 + tx] = tile[tx][r];
}

// ---------------------------------------------------------------------------
// Persistent fused LSTM: 128 CTAs x 16 batch rows, 64 timesteps, no grid sync.
// Thread t owns hidden units k0=2t, k0+1 (all 4 gates, all 16 batch rows).
// acc[g][u][bp] : f32x2 accumulator, lanes = batch pair (2bp, 2bp+1).
// h lives in smem (broadcast reads in j-loop); c is thread-private in smem.
// ---------------------------------------------------------------------------
#define SMEM_BYTES (HH * 9 * 8 * 2 + AA * HH * 4)  // hs + cs (float2, pad 9) + W_out

__global__ void __launch_bounds__(256, 1)
lstm_kernel(const float* __restrict__ W_out,
            const float* __restrict__ b_out,
            float* __restrict__ out) {
    extern __shared__ char smem_raw[];
    float2* hs = (float2*)smem_raw;          // [k][bp], row stride 9 (pad)
    float2* cs = hs + HH * 9;                // same layout
    float*  ws = (float*)(cs + HH * 9);      // W_out copy [a*H + k]

    const int tid = threadIdx.x;
    const int b0 = blockIdx.x * 16;
    const int k0 = 2 * tid;

    for (int i = tid; i < AA * HH; i += 256) ws[i] = W_out[i];
    for (int i = tid; i < HH * 9; i += 256) {
        hs[i] = make_float2(0.f, 0.f);
        cs[i] = make_float2(0.f, 0.f);
    }
    const float bo = (tid < 128) ? b_out[tid >> 4] : 0.f;
    __syncthreads();

    u64 acc[4][2][8];

    for (int step = 0; step < TT; ++step) {
        // --- init accumulators from precomputed x_proj ---
#pragma unroll
        for (int g = 0; g < 4; ++g)
#pragma unroll
            for (int u = 0; u < 2; ++u) {
                const float4* xp4 =
                    (const float4*)(g_xproj + (g * HH + k0 + u) * BB + b0);
#pragma unroll
                for (int q = 0; q < 4; ++q) {
                    float4 v = xp4[q];
                    acc[g][u][2 * q + 0] = pack2(v.x, v.y);
                    acc[g][u][2 * q + 1] = pack2(v.z, v.w);
                }
            }

        // --- recurrent matvec: acc[g][u][bp] += W_hh[g*H+k0+u][j] * h[b][j] ---
        // 1-deep software pipeline on W (L2 latency) and h (smem latency).
        {
            const float* wbase = g_WT + k0;
            float2 wcur[4];
            u64 hcur[8];
#pragma unroll
            for (int g = 0; g < 4; ++g)
                wcur[g] = *(const float2*)(wbase + g * HH);
#pragma unroll
            for (int bp = 0; bp < 8; ++bp) hcur[bp] = *(const u64*)&hs[0 * 9 + bp];

            for (int j = 0; j < HH; ++j) {
                const int jn = (j + 1) & (HH - 1);  // wraps to 0 on last iter (unused)
                float2 wnxt[4];
                u64 hnxt[8];
                const float* wr = wbase + jn * FOURH;
#pragma unroll
                for (int g = 0; g < 4; ++g) wnxt[g] = *(const float2*)(wr + g * HH);
#pragma unroll
                for (int bp = 0; bp < 8; ++bp)
                    hnxt[bp] = *(const u64*)&hs[jn * 9 + bp];

#pragma unroll
                for (int g = 0; g < 4; ++g) {
                    const u64 w0 = pack2(wcur[g].x, wcur[g].x);
                    const u64 w1 = pack2(wcur[g].y, wcur[g].y);
#pragma unroll
                    for (int bp = 0; bp < 8; ++bp) {
                        acc[g][0][bp] = fma2(w0, hcur[bp], acc[g][0][bp]);
                        acc[g][1][bp] = fma2(w1, hcur[bp], acc[g][1][bp]);
                    }
                }
#pragma unroll
                for (int g = 0; g < 4; ++g) wcur[g] = wnxt[g];
#pragma unroll
                for (int bp = 0; bp < 8; ++bp) hcur[bp] = hnxt[bp];
            }
        }

        __syncthreads();  // all reads of hs done before overwriting

        // --- cell update (thread-private units) ---
#pragma unroll
        for (int u = 0; u < 2; ++u) {
            const int k = k0 + u;
#pragma unroll
            for (int bp = 0; bp < 8; ++bp) {
                float2 iv = unpack2(acc[0][u][bp]);
                float2 fv = unpack2(acc[1][u][bp]);
                float2 gv = unpack2(acc[2][u][bp]);
                float2 ov = unpack2(acc[3][u][bp]);
                float2 co = cs[k * 9 + bp];
                float2 cn, hn;
                cn.x = sigf(fv.x) * co.x + sigf(iv.x) * thf(gv.x);
                cn.y = sigf(fv.y) * co.y + sigf(iv.y) * thf(gv.y);
                hn.x = sigf(ov.x) * thf(cn.x);
                hn.y = sigf(ov.y) * thf(cn.y);
                cs[k * 9 + bp] = cn;
                hs[k * 9 + bp] = hn;
            }
        }
        __syncthreads();  // h(t) visible to everyone

        // --- fused output head: out[b][step][a] = b_out[a] + W_out[a,:] . h[b,:] ---
        if (tid < 128) {
            const int a = tid >> 4;
            const int bi = tid & 15;
            const int bp = bi >> 1;
            const int hi = bi & 1;
            float sum = 0.f;
#pragma unroll 8
            for (int k = 0; k < HH; ++k) {
                float2 hv2 = hs[k * 9 + bp];
                float hv = hi ? hv2.y : hv2.x;
                sum = fmaf(ws[a * HH + k], hv, sum);
            }
            out[(b0 + bi) * (TT * AA) + step * AA + a] = sum + bo;
        }
        // No extra sync needed: hs isn't written again until after the next
        // j-loop's __syncthreads, which these threads reach after projecting.
    }
}

// ---------------------------------------------------------------------------
extern "C" void kernel_launch(void* const* d_in, const int* in_sizes, int n_in,
                              void* d_out, int out_size) {
    const float* z     = (const float*)d_in[0];
    const float* W_ih  = (const float*)d_in[1];
    const float* W_hh  = (const float*)d_in[2];
    const float* b_ih  = (const float*)d_in[3];
    const float* b_hh  = (const float*)d_in[4];
    const float* W_out = (const float*)d_in[5];
    const float* b_out = (const float*)d_in[6];
    float* out = (float*)d_out;
    (void)in_sizes; (void)n_in; (void)out_size;

    xproj_kernel<<<dim3(BB / 128, FOURH / 128), 256>>>(z, W_ih, b_ih, b_hh);
    transpose_kernel<<<dim3(FOURH / 32, HH / 32), dim3(32, 8)>>>(W_hh);

    cudaFuncSetAttribute(lstm_kernel,
                         cudaFuncAttributeMaxDynamicSharedMemorySize, SMEM_BYTES);
    lstm_kernel<<<128, 256, SMEM_BYTES>>>(W_out, b_out, out);
}

// round 2
// speedup vs baseline: 1.0003x; 1.0003x over previous
#include <cuda_runtime.h>

#define BB    2048
#define ZZ    64
#define AA    8
#define HH    512
#define TT    64
#define FOURH 2048

// Scratch (device globals — no allocation allowed)
__device__ float g_xproj[FOURH * BB];   // [n][b]  16 MB: x_proj transposed, batch contiguous
__device__ float g_WT[HH * FOURH];      // [j][n]   4 MB: W_hh transposed, n contiguous

typedef unsigned long long u64;

__device__ __forceinline__ u64 fma2(u64 a, u64 b, u64 c) {
    u64 d;
    asm("fma.rn.f32x2 %0, %1, %2, %3;" : "=l"(d) : "l"(a), "l"(b), "l"(c));
    return d;
}
__device__ __forceinline__ u64 pack2(float x, float y) {
    u64 d;
    asm("mov.b64 %0, {%1, %2};" : "=l"(d) : "f"(x), "f"(y));
    return d;
}
__device__ __forceinline__ float2 unpack2(u64 v) {
    float2 r;
    asm("mov.b64 {%0, %1}, %2;" : "=f"(r.x), "=f"(r.y) : "l"(v));
    return r;
}

__device__ __forceinline__ float sigf(float x) {
    return __fdividef(1.f, 1.f + __expf(-x));
}
__device__ __forceinline__ float thf(float x) {
    float xx = fminf(fmaxf(x, -15.f), 15.f);
    float e = __expf(-2.f * xx);
    return __fdividef(1.f - e, 1.f + e);
}

// ---------------------------------------------------------------------------
// x_proj[n][b] = b_ih[n] + b_hh[n] + sum_j z[b][j] * W_ih[n][A+j]
// (first A input columns are zeros in the reference -> skipped)
// grid: (B/128, 4H/128), block 256
// ---------------------------------------------------------------------------
__global__ void xproj_kernel(const float* __restrict__ z,
                             const float* __restrict__ W_ih,
                             const float* __restrict__ b_ih,
                             const float* __restrict__ b_hh) {
    __shared__ float zs[128][ZZ + 1];
    const int b0 = blockIdx.x * 128;
    const int n0 = blockIdx.y * 128;
    const int tid = threadIdx.x;

    for (int i = tid; i < 128 * ZZ; i += 256) {
        int bi = i / ZZ, j = i % ZZ;
        zs[bi][j] = z[(b0 + bi) * ZZ + j];
    }
    __syncthreads();

    const int bi = tid & 127;
    const int nhalf = tid >> 7;  // 0..1
    for (int nn = 0; nn < 64; ++nn) {
        const int n = n0 + nhalf * 64 + nn;
        const float* w = W_ih + n * (AA + ZZ) + AA;
        float acc = b_ih[n] + b_hh[n];
#pragma unroll 8
        for (int j = 0; j < ZZ; ++j) acc = fmaf(w[j], zs[bi][j], acc);
        g_xproj[n * BB + b0 + bi] = acc;
    }
}

// ---------------------------------------------------------------------------
// g_WT[j][n] = W_hh[n][j]   (tiled transpose)
// grid: (4H/32, H/32), block (32,8)
// ---------------------------------------------------------------------------
__global__ void transpose_kernel(const float* __restrict__ W_hh) {
    __shared__ float tile[32][33];
    const int n0 = blockIdx.x * 32;
    const int j0 = blockIdx.y * 32;
    const int tx = threadIdx.x, ty = threadIdx.y;
    for (int r = ty; r < 32; r += 8)
        tile[r][tx] = W_hh[(n0 + r) * HH + j0 + tx];
    __syncthreads();
    for (int r = ty; r < 32; r += 8)
        g_WT[(j0 + r) * FOURH + n0 + tx] = tile[tx][r];
}

// ---------------------------------------------------------------------------
// Persistent fused LSTM: 128 CTAs x 16 batch rows, 64 timesteps, no grid sync.
// Thread t owns hidden units k0=2t, k0+1 (all 4 gates, all 16 batch rows).
// acc[g][u][bp] : f32x2 accumulator, lanes = batch pair (2bp, 2bp+1).
// h lives in smem (broadcast reads in j-loop); c is thread-private in smem.
// ---------------------------------------------------------------------------
#define SMEM_BYTES (HH * 9 * 8 * 2 + AA * HH * 4)  // hs + cs (float2, pad 9) + W_out

__global__ void __launch_bounds__(256, 1)
lstm_kernel(const float* __restrict__ W_out,
            const float* __restrict__ b_out,
            float* __restrict__ out) {
    extern __shared__ char smem_raw[];
    float2* hs = (float2*)smem_raw;          // [k][bp], row stride 9 (pad)
    float2* cs = hs + HH * 9;                // same layout
    float*  ws = (float*)(cs + HH * 9);      // W_out copy [a*H + k]

    const int tid = threadIdx.x;
    const int b0 = blockIdx.x * 16;
    const int k0 = 2 * tid;

    for (int i = tid; i < AA * HH; i += 256) ws[i] = W_out[i];
    for (int i = tid; i < HH * 9; i += 256) {
        hs[i] = make_float2(0.f, 0.f);
        cs[i] = make_float2(0.f, 0.f);
    }
    const float bo = (tid < 128) ? b_out[tid >> 4] : 0.f;
    __syncthreads();

    u64 acc[4][2][8];

    for (int step = 0; step < TT; ++step) {
        // --- init accumulators from precomputed x_proj ---
#pragma unroll
        for (int g = 0; g < 4; ++g)
#pragma unroll
            for (int u = 0; u < 2; ++u) {
                const float4* xp4 =
                    (const float4*)(g_xproj + (g * HH + k0 + u) * BB + b0);
#pragma unroll
                for (int q = 0; q < 4; ++q) {
                    float4 v = xp4[q];
                    acc[g][u][2 * q + 0] = pack2(v.x, v.y);
                    acc[g][u][2 * q + 1] = pack2(v.z, v.w);
                }
            }

        // --- recurrent matvec: acc[g][u][bp] += W_hh[g*H+k0+u][j] * h[b][j] ---
        // 1-deep software pipeline on W (L2 latency) and h (smem latency).
        {
            const float* wbase = g_WT + k0;
            float2 wcur[4];
            u64 hcur[8];
#pragma unroll
            for (int g = 0; g < 4; ++g)
                wcur[g] = *(const float2*)(wbase + g * HH);
#pragma unroll
            for (int bp = 0; bp < 8; ++bp) hcur[bp] = *(const u64*)&hs[0 * 9 + bp];

            for (int j = 0; j < HH; ++j) {
                const int jn = (j + 1) & (HH - 1);  // wraps to 0 on last iter (unused)
                float2 wnxt[4];
                u64 hnxt[8];
                const float* wr = wbase + jn * FOURH;
#pragma unroll
                for (int g = 0; g < 4; ++g) wnxt[g] = *(const float2*)(wr + g * HH);
#pragma unroll
                for (int bp = 0; bp < 8; ++bp)
                    hnxt[bp] = *(const u64*)&hs[jn * 9 + bp];

#pragma unroll
                for (int g = 0; g < 4; ++g) {
                    const u64 w0 = pack2(wcur[g].x, wcur[g].x);
                    const u64 w1 = pack2(wcur[g].y, wcur[g].y);
#pragma unroll
                    for (int bp = 0; bp < 8; ++bp) {
                        acc[g][0][bp] = fma2(w0, hcur[bp], acc[g][0][bp]);
                        acc[g][1][bp] = fma2(w1, hcur[bp], acc[g][1][bp]);
                    }
                }
#pragma unroll
                for (int g = 0; g < 4; ++g) wcur[g] = wnxt[g];
#pragma unroll
                for (int bp = 0; bp < 8; ++bp) hcur[bp] = hnxt[bp];
            }
        }

        __syncthreads();  // all reads of hs done before overwriting

        // --- cell update (thread-private units) ---
#pragma unroll
        for (int u = 0; u < 2; ++u) {
            const int k = k0 + u;
#pragma unroll
            for (int bp = 0; bp < 8; ++bp) {
                float2 iv = unpack2(acc[0][u][bp]);
                float2 fv = unpack2(acc[1][u][bp]);
                float2 gv = unpack2(acc[2][u][bp]);
                float2 ov = unpack2(acc[3][u][bp]);
                float2 co = cs[k * 9 + bp];
                float2 cn, hn;
                cn.x = sigf(fv.x) * co.x + sigf(iv.x) * thf(gv.x);
                cn.y = sigf(fv.y) * co.y + sigf(iv.y) * thf(gv.y);
                hn.x = sigf(ov.x) * thf(cn.x);
                hn.y = sigf(ov.y) * thf(cn.y);
                cs[k * 9 + bp] = cn;
                hs[k * 9 + bp] = hn;
            }
        }
        __syncthreads();  // h(t) visible to everyone

        // --- fused output head: out[b][step][a] = b_out[a] + W_out[a,:] . h[b,:] ---
        if (tid < 128) {
            const int a = tid >> 4;
            const int bi = tid & 15;
            const int bp = bi >> 1;
            const int hi = bi & 1;
            float sum = 0.f;
#pragma unroll 8
            for (int k = 0; k < HH; ++k) {
                float2 hv2 = hs[k * 9 + bp];
                float hv = hi ? hv2.y : hv2.x;
                sum = fmaf(ws[a * HH + k], hv, sum);
            }
            out[(b0 + bi) * (TT * AA) + step * AA + a] = sum + bo;
        }
        // No extra sync needed: hs isn't written again until after the next
        // j-loop's __syncthreads, which these threads reach after projecting.
    }
}

// ---------------------------------------------------------------------------
extern "C" void kernel_launch(void* const* d_in, const int* in_sizes, int n_in,
                              void* d_out, int out_size) {
    const float* z     = (const float*)d_in[0];
    const float* W_ih  = (const float*)d_in[1];
    const float* W_hh  = (const float*)d_in[2];
    const float* b_ih  = (const float*)d_in[3];
    const float* b_hh  = (const float*)d_in[4];
    const float* W_out = (const float*)d_in[5];
    const float* b_out = (const float*)d_in[6];
    float* out = (float*)d_out;
    (void)in_sizes; (void)n_in; (void)out_size;

    xproj_kernel<<<dim3(BB / 128, FOURH / 128), 256>>>(z, W_ih, b_ih, b_hh);
    transpose_kernel<<<dim3(FOURH / 32, HH / 32), dim3(32, 8)>>>(W_hh);

    cudaFuncSetAttribute(lstm_kernel,
                         cudaFuncAttributeMaxDynamicSharedMemorySize, SMEM_BYTES);
    lstm_kernel<<<128, 256, SMEM_BYTES>>>(W_out, b_out, out);
}

// round 3
// speedup vs baseline: 1.0009x; 1.0007x over previous
#include <cuda_runtime.h>

#define BB    2048
#define ZZ    64
#define AA    8
#define HH    512
#define TT    64
#define FOURH 2048

// Scratch (device globals — no allocation allowed)
__device__ float g_xproj[FOURH * BB];   // [n][b]  16 MB: x_proj transposed, batch contiguous
__device__ float g_WT[HH * FOURH];      // [j][n]   4 MB: W_hh transposed, n contiguous

typedef unsigned long long u64;

__device__ __forceinline__ u64 fma2(u64 a, u64 b, u64 c) {
    u64 d;
    asm("fma.rn.f32x2 %0, %1, %2, %3;" : "=l"(d) : "l"(a), "l"(b), "l"(c));
    return d;
}
__device__ __forceinline__ u64 pack2(float x, float y) {
    u64 d;
    asm("mov.b64 %0, {%1, %2};" : "=l"(d) : "f"(x), "f"(y));
    return d;
}
__device__ __forceinline__ float2 unpack2(u64 v) {
    float2 r;
    asm("mov.b64 {%0, %1}, %2;" : "=f"(r.x), "=f"(r.y) : "l"(v));
    return r;
}

__device__ __forceinline__ float sigf(float x) {
    return __fdividef(1.f, 1.f + __expf(-x));
}
__device__ __forceinline__ float thf(float x) {
    float xx = fminf(fmaxf(x, -15.f), 15.f);
    float e = __expf(-2.f * xx);
    return __fdividef(1.f - e, 1.f + e);
}

// ---------------------------------------------------------------------------
// x_proj[n][b] = b_ih[n] + b_hh[n] + sum_j z[b][j] * W_ih[n][A+j]
// (first A input columns are zeros in the reference -> skipped)
// grid: (B/128, 4H/128), block 256
// ---------------------------------------------------------------------------
__global__ void xproj_kernel(const float* __restrict__ z,
                             const float* __restrict__ W_ih,
                             const float* __restrict__ b_ih,
                             const float* __restrict__ b_hh) {
    __shared__ float zs[128][ZZ + 1];
    const int b0 = blockIdx.x * 128;
    const int n0 = blockIdx.y * 128;
    const int tid = threadIdx.x;

    for (int i = tid; i < 128 * ZZ; i += 256) {
        int bi = i / ZZ, j = i % ZZ;
        zs[bi][j] = z[(b0 + bi) * ZZ + j];
    }
    __syncthreads();

    const int bi = tid & 127;
    const int nhalf = tid >> 7;  // 0..1
    for (int nn = 0; nn < 64; ++nn) {
        const int n = n0 + nhalf * 64 + nn;
        const float* w = W_ih + n * (AA + ZZ) + AA;
        float acc = b_ih[n] + b_hh[n];
#pragma unroll 8
        for (int j = 0; j < ZZ; ++j) acc = fmaf(w[j], zs[bi][j], acc);
        g_xproj[n * BB + b0 + bi] = acc;
    }
}

// ---------------------------------------------------------------------------
// g_WT[j][n] = W_hh[n][j]   (tiled transpose)
// grid: (4H/32, H/32), block (32,8)
// ---------------------------------------------------------------------------
__global__ void transpose_kernel(const float* __restrict__ W_hh) {
    __shared__ float tile[32][33];
    const int n0 = blockIdx.x * 32;
    const int j0 = blockIdx.y * 32;
    const int tx = threadIdx.x, ty = threadIdx.y;
    for (int r = ty; r < 32; r += 8)
        tile[r][tx] = W_hh[(n0 + r) * HH + j0 + tx];
    __syncthreads();
    for (int r = ty; r < 32; r += 8)
        g_WT[(j0 + r) * FOURH + n0 + tx] = tile[tx][r];
}

// ---------------------------------------------------------------------------
// Persistent fused LSTM: 128 CTAs x 16 batch rows, 64 timesteps, no grid sync.
// Thread t owns hidden units k0=2t, k0+1 (all 4 gates, all 16 batch rows).
// acc[g][u][bp] : f32x2 accumulator, lanes = batch pair (2bp, 2bp+1).
// h lives in smem (broadcast reads in j-loop); c is thread-private in smem.
// ---------------------------------------------------------------------------
#define SMEM_BYTES (HH * 9 * 8 * 2 + AA * HH * 4)  // hs + cs (float2, pad 9) + W_out

__global__ void __launch_bounds__(256, 1)
lstm_kernel(const float* __restrict__ W_out,
            const float* __restrict__ b_out,
            float* __restrict__ out) {
    extern __shared__ char smem_raw[];
    float2* hs = (float2*)smem_raw;          // [k][bp], row stride 9 (pad)
    float2* cs = hs + HH * 9;                // same layout
    float*  ws = (float*)(cs + HH * 9);      // W_out copy [a*H + k]

    const int tid = threadIdx.x;
    const int b0 = blockIdx.x * 16;
    const int k0 = 2 * tid;

    for (int i = tid; i < AA * HH; i += 256) ws[i] = W_out[i];
    for (int i = tid; i < HH * 9; i += 256) {
        hs[i] = make_float2(0.f, 0.f);
        cs[i] = make_float2(0.f, 0.f);
    }
    const float bo = (tid < 128) ? b_out[tid >> 4] : 0.f;
    __syncthreads();

    u64 acc[4][2][8];

    for (int step = 0; step < TT; ++step) {
        // --- init accumulators from precomputed x_proj ---
#pragma unroll
        for (int g = 0; g < 4; ++g)
#pragma unroll
            for (int u = 0; u < 2; ++u) {
                const float4* xp4 =
                    (const float4*)(g_xproj + (g * HH + k0 + u) * BB + b0);
#pragma unroll
                for (int q = 0; q < 4; ++q) {
                    float4 v = xp4[q];
                    acc[g][u][2 * q + 0] = pack2(v.x, v.y);
                    acc[g][u][2 * q + 1] = pack2(v.z, v.w);
                }
            }

        // --- recurrent matvec: acc[g][u][bp] += W_hh[g*H+k0+u][j] * h[b][j] ---
        // 1-deep software pipeline on W (L2 latency) and h (smem latency).
        {
            const float* wbase = g_WT + k0;
            float2 wcur[4];
            u64 hcur[8];
#pragma unroll
            for (int g = 0; g < 4; ++g)
                wcur[g] = *(const float2*)(wbase + g * HH);
#pragma unroll
            for (int bp = 0; bp < 8; ++bp) hcur[bp] = *(const u64*)&hs[0 * 9 + bp];

            for (int j = 0; j < HH; ++j) {
                const int jn = (j + 1) & (HH - 1);  // wraps to 0 on last iter (unused)
                float2 wnxt[4];
                u64 hnxt[8];
                const float* wr = wbase + jn * FOURH;
#pragma unroll
                for (int g = 0; g < 4; ++g) wnxt[g] = *(const float2*)(wr + g * HH);
#pragma unroll
                for (int bp = 0; bp < 8; ++bp)
                    hnxt[bp] = *(const u64*)&hs[jn * 9 + bp];

#pragma unroll
                for (int g = 0; g < 4; ++g) {
                    const u64 w0 = pack2(wcur[g].x, wcur[g].x);
                    const u64 w1 = pack2(wcur[g].y, wcur[g].y);
#pragma unroll
                    for (int bp = 0; bp < 8; ++bp) {
                        acc[g][0][bp] = fma2(w0, hcur[bp], acc[g][0][bp]);
                        acc[g][1][bp] = fma2(w1, hcur[bp], acc[g][1][bp]);
                    }
                }
#pragma unroll
                for (int g = 0; g < 4; ++g) wcur[g] = wnxt[g];
#pragma unroll
                for (int bp = 0; bp < 8; ++bp) hcur[bp] = hnxt[bp];
            }
        }

        __syncthreads();  // all reads of hs done before overwriting

        // --- cell update (thread-private units) ---
#pragma unroll
        for (int u = 0; u < 2; ++u) {
            const int k = k0 + u;
#pragma unroll
            for (int bp = 0; bp < 8; ++bp) {
                float2 iv = unpack2(acc[0][u][bp]);
                float2 fv = unpack2(acc[1][u][bp]);
                float2 gv = unpack2(acc[2][u][bp]);
                float2 ov = unpack2(acc[3][u][bp]);
                float2 co = cs[k * 9 + bp];
                float2 cn, hn;
                cn.x = sigf(fv.x) * co.x + sigf(iv.x) * thf(gv.x);
                cn.y = sigf(fv.y) * co.y + sigf(iv.y) * thf(gv.y);
                hn.x = sigf(ov.x) * thf(cn.x);
                hn.y = sigf(ov.y) * thf(cn.y);
                cs[k * 9 + bp] = cn;
                hs[k * 9 + bp] = hn;
            }
        }
        __syncthreads();  // h(t) visible to everyone

        // --- fused output head: out[b][step][a] = b_out[a] + W_out[a,:] . h[b,:] ---
        if (tid < 128) {
            const int a = tid >> 4;
            const int bi = tid & 15;
            const int bp = bi >> 1;
            const int hi = bi & 1;
            float sum = 0.f;
#pragma unroll 8
            for (int k = 0; k < HH; ++k) {
                float2 hv2 = hs[k * 9 + bp];
                float hv = hi ? hv2.y : hv2.x;
                sum = fmaf(ws[a * HH + k], hv, sum);
            }
            out[(b0 + bi) * (TT * AA) + step * AA + a] = sum + bo;
        }
        // No extra sync needed: hs isn't written again until after the next
        // j-loop's __syncthreads, which these threads reach after projecting.
    }
}

// ---------------------------------------------------------------------------
extern "C" void kernel_launch(void* const* d_in, const int* in_sizes, int n_in,
                              void* d_out, int out_size) {
    const float* z     = (const float*)d_in[0];
    const float* W_ih  = (const float*)d_in[1];
    const float* W_hh  = (const float*)d_in[2];
    const float* b_ih  = (const float*)d_in[3];
    const float* b_hh  = (const float*)d_in[4];
    const float* W_out = (const float*)d_in[5];
    const float* b_out = (const float*)d_in[6];
    float* out = (float*)d_out;
    (void)in_sizes; (void)n_in; (void)out_size;

    xproj_kernel<<<dim3(BB / 128, FOURH / 128), 256>>>(z, W_ih, b_ih, b_hh);
    transpose_kernel<<<dim3(FOURH / 32, HH / 32), dim3(32, 8)>>>(W_hh);

    cudaFuncSetAttribute(lstm_kernel,
                         cudaFuncAttributeMaxDynamicSharedMemorySize, SMEM_BYTES);
    lstm_kernel<<<128, 256, SMEM_BYTES>>>(W_out, b_out, out);
}